// round 2
// baseline (speedup 1.0000x reference)
#include <cuda_runtime.h>

// ---------------------------------------------------------------------------
// ViewGCNEncoder: 3-layer GCN
//   per layer: h = A_in @ W^T + b  (dense GEMM, NT form)
//              s = SpMM(adj, h)    (segment-sum over edges, CSR, atomic-free)
//              s = leaky_relu(s); s = mask ? s*1.25 : 0   (layers 1,2 only)
// Masks are read as 4-byte words (nonzero test) — correct for both int32 and
// float32 widenings of the original bool arrays.
// Output: z[N,64] f32
// ---------------------------------------------------------------------------

#define NMAX 50000
#define EMAX 800000

// Scratch (device globals: allocation-free rule)
__device__ float g_bufA[(size_t)NMAX * 256];
__device__ float g_bufB[(size_t)NMAX * 256];
__device__ int   g_cnt[NMAX];
__device__ int   g_rowptr[NMAX + 1];
__device__ int   g_cursor[NMAX];
__device__ int   g_ecol[EMAX];
__device__ float g_eval[EMAX];

// ---------------------------------------------------------------------------
// CSR construction (rebuilt every launch: determinism rule forbids caching)
// ---------------------------------------------------------------------------
__global__ void zero_cnt_kernel(int n) {
    int i = blockIdx.x * blockDim.x + threadIdx.x;
    if (i < n) g_cnt[i] = 0;
}

__global__ void hist_kernel(const int* __restrict__ rows, int E) {
    int i = blockIdx.x * blockDim.x + threadIdx.x;
    if (i < E) atomicAdd(&g_cnt[rows[i]], 1);
}

// Single-block exclusive scan over g_cnt -> g_rowptr (and g_cursor copy)
__global__ void scan_kernel(int n) {
    __shared__ int partial[1024];
    int tid = threadIdx.x;
    int chunk = (n + 1023) >> 10;
    int beg = tid * chunk;
    int end = min(beg + chunk, n);
    int sum = 0;
    for (int i = beg; i < end; ++i) sum += g_cnt[i];
    partial[tid] = sum;
    __syncthreads();
    for (int d = 1; d < 1024; d <<= 1) {
        int add = (tid >= d) ? partial[tid - d] : 0;
        __syncthreads();
        partial[tid] += add;
        __syncthreads();
    }
    int run = partial[tid] - sum;  // exclusive prefix
    for (int i = beg; i < end; ++i) {
        g_rowptr[i] = run;
        g_cursor[i] = run;
        run += g_cnt[i];
    }
    if (beg < n && end == n) g_rowptr[n] = run;
}

__global__ void scatter_kernel(const int* __restrict__ rows, const int* __restrict__ cols,
                               const float* __restrict__ vals, int E) {
    int i = blockIdx.x * blockDim.x + threadIdx.x;
    if (i < E) {
        int r = rows[i];
        int pos = atomicAdd(&g_cursor[r], 1);
        g_ecol[pos] = cols[i];
        g_eval[pos] = vals[i];
    }
}

// ---------------------------------------------------------------------------
// Dense GEMM: C[N,ODIM] = A[N,KDIM] @ W[ODIM,KDIM]^T + bias
// 128x64 block tile, BK=32, 256 threads, 8x4 per-thread tile, fp32 FFMA.
// ---------------------------------------------------------------------------
template <int KDIM, int ODIM>
__global__ __launch_bounds__(256) void gemm_bias_kernel(
    const float* __restrict__ A, const float* __restrict__ W,
    const float* __restrict__ bias, float* __restrict__ C, int N)
{
    constexpr int BM = 128, BN = 64, BK = 32;
    __shared__ float As[BK][BM];
    __shared__ float Ws[BK][BN];

    const int tid = threadIdx.x;
    const int m0 = blockIdx.x * BM;
    const int o0 = blockIdx.y * BN;
    const int tx = tid & 15;   // N dim: 16 threads * 4 cols
    const int ty = tid >> 4;   // M dim: 16 threads * 8 rows

    float acc[8][4];
#pragma unroll
    for (int i = 0; i < 8; ++i)
#pragma unroll
        for (int j = 0; j < 4; ++j) acc[i][j] = 0.f;

    const int ldrow = tid >> 3;        // 0..31
    const int ldk   = (tid & 7) * 4;   // 0,4,...,28

    for (int k0 = 0; k0 < KDIM; k0 += BK) {
        // A tile 128x32 (transposed into As[k][m]), guarded on rows
#pragma unroll
        for (int r = 0; r < 4; ++r) {
            int mrow = ldrow + 32 * r;
            int m = m0 + mrow;
            float4 v = make_float4(0.f, 0.f, 0.f, 0.f);
            if (m < N) v = *(const float4*)&A[(size_t)m * KDIM + k0 + ldk];
            As[ldk + 0][mrow] = v.x;
            As[ldk + 1][mrow] = v.y;
            As[ldk + 2][mrow] = v.z;
            As[ldk + 3][mrow] = v.w;
        }
        // W tile 64x32 (always in-bounds: ODIM multiple of 64)
#pragma unroll
        for (int r = 0; r < 2; ++r) {
            int orow = ldrow + 32 * r;
            float4 v = *(const float4*)&W[(size_t)(o0 + orow) * KDIM + k0 + ldk];
            Ws[ldk + 0][orow] = v.x;
            Ws[ldk + 1][orow] = v.y;
            Ws[ldk + 2][orow] = v.z;
            Ws[ldk + 3][orow] = v.w;
        }
        __syncthreads();

#pragma unroll
        for (int kk = 0; kk < BK; ++kk) {
            float ra[8], rw[4];
            *(float4*)&ra[0] = *(float4*)&As[kk][ty * 8];
            *(float4*)&ra[4] = *(float4*)&As[kk][ty * 8 + 4];
            *(float4*)&rw[0] = *(float4*)&Ws[kk][tx * 4];
#pragma unroll
            for (int i = 0; i < 8; ++i)
#pragma unroll
                for (int j = 0; j < 4; ++j)
                    acc[i][j] += ra[i] * rw[j];
        }
        __syncthreads();
    }

    float4 bv = *(const float4*)&bias[o0 + tx * 4];
#pragma unroll
    for (int i = 0; i < 8; ++i) {
        int m = m0 + ty * 8 + i;
        if (m < N) {
            float4 o;
            o.x = acc[i][0] + bv.x;
            o.y = acc[i][1] + bv.y;
            o.z = acc[i][2] + bv.z;
            o.w = acc[i][3] + bv.w;
            *(float4*)&C[(size_t)m * ODIM + o0 + tx * 4] = o;
        }
    }
}

// ---------------------------------------------------------------------------
// CSR SpMM, warp-per-row, atomic-free, fused LeakyReLU + dropout mask.
//   out[r,:] = sum_e val[e] * H[col[e],:]    (then activation/mask if enabled)
// Mask elements are 4-byte words; nonzero == keep.
// ---------------------------------------------------------------------------
__device__ __forceinline__ float leaky(float x) { return x >= 0.f ? x : 0.2f * x; }

template <int D, bool HAS_MASK>
__global__ __launch_bounds__(256) void spmm_kernel(
    const float* __restrict__ H, const unsigned int* __restrict__ mask,
    float* __restrict__ out, int N)
{
    const int warp = (blockIdx.x * blockDim.x + threadIdx.x) >> 5;
    const int lane = threadIdx.x & 31;
    if (warp >= N) return;
    const int r = warp;
    const int start = g_rowptr[r];
    const int end   = g_rowptr[r + 1];

    constexpr int V = D / 32;  // 8, 4, or 2 floats per lane
    float acc[V];
#pragma unroll
    for (int v = 0; v < V; ++v) acc[v] = 0.f;

    for (int base = start; base < end; base += 32) {
        int e = base + lane;
        int c = 0;
        float v = 0.f;
        if (e < end) { c = g_ecol[e]; v = g_eval[e]; }
        int cnt = min(32, end - base);
#pragma unroll 4
        for (int j = 0; j < cnt; ++j) {
            int   cj = __shfl_sync(0xffffffffu, c, j);
            float vj = __shfl_sync(0xffffffffu, v, j);
            const float* hp = H + (size_t)cj * D;
            if (D == 256) {
                float4 a = *(const float4*)&hp[lane * 4];
                float4 b = *(const float4*)&hp[128 + lane * 4];
                acc[0] += vj * a.x; acc[1] += vj * a.y;
                acc[2] += vj * a.z; acc[3] += vj * a.w;
                acc[4] += vj * b.x; acc[5] += vj * b.y;
                acc[6] += vj * b.z; acc[7] += vj * b.w;
            } else if (D == 128) {
                float4 a = *(const float4*)&hp[lane * 4];
                acc[0] += vj * a.x; acc[1] += vj * a.y;
                acc[2] += vj * a.z; acc[3] += vj * a.w;
            } else {  // D == 64
                float2 a = *(const float2*)&hp[lane * 2];
                acc[0] += vj * a.x; acc[1] += vj * a.y;
            }
        }
    }

    const float keep = 1.25f;  // 1/(1-0.2)
    if (D == 256) {
        float4 o0, o1;
        if (HAS_MASK) {
            uint4 m0 = *(const uint4*)&mask[(size_t)r * D + lane * 4];
            uint4 m1 = *(const uint4*)&mask[(size_t)r * D + 128 + lane * 4];
            o0.x = m0.x ? leaky(acc[0]) * keep : 0.f;
            o0.y = m0.y ? leaky(acc[1]) * keep : 0.f;
            o0.z = m0.z ? leaky(acc[2]) * keep : 0.f;
            o0.w = m0.w ? leaky(acc[3]) * keep : 0.f;
            o1.x = m1.x ? leaky(acc[4]) * keep : 0.f;
            o1.y = m1.y ? leaky(acc[5]) * keep : 0.f;
            o1.z = m1.z ? leaky(acc[6]) * keep : 0.f;
            o1.w = m1.w ? leaky(acc[7]) * keep : 0.f;
        } else {
            o0 = make_float4(acc[0], acc[1], acc[2], acc[3]);
            o1 = make_float4(acc[4], acc[5], acc[6], acc[7]);
        }
        *(float4*)&out[(size_t)r * D + lane * 4] = o0;
        *(float4*)&out[(size_t)r * D + 128 + lane * 4] = o1;
    } else if (D == 128) {
        float4 o0;
        if (HAS_MASK) {
            uint4 m0 = *(const uint4*)&mask[(size_t)r * D + lane * 4];
            o0.x = m0.x ? leaky(acc[0]) * keep : 0.f;
            o0.y = m0.y ? leaky(acc[1]) * keep : 0.f;
            o0.z = m0.z ? leaky(acc[2]) * keep : 0.f;
            o0.w = m0.w ? leaky(acc[3]) * keep : 0.f;
        } else {
            o0 = make_float4(acc[0], acc[1], acc[2], acc[3]);
        }
        *(float4*)&out[(size_t)r * D + lane * 4] = o0;
    } else {  // D == 64, final layer: no activation, no mask
        float2 o0 = make_float2(acc[0], acc[1]);
        *(float2*)&out[(size_t)r * D + lane * 2] = o0;
    }
}

// ---------------------------------------------------------------------------
// Launch
// ---------------------------------------------------------------------------
extern "C" void kernel_launch(void* const* d_in, const int* in_sizes, int n_in,
                              void* d_out, int out_size)
{
    const float* x     = (const float*)d_in[0];
    const int*   rows  = (const int*)d_in[1];
    const int*   cols  = (const int*)d_in[2];
    const float* vals  = (const float*)d_in[3];
    const float* W1    = (const float*)d_in[4];
    const float* b1    = (const float*)d_in[5];
    const float* W2    = (const float*)d_in[6];
    const float* b2    = (const float*)d_in[7];
    const float* W3    = (const float*)d_in[8];
    const float* b3    = (const float*)d_in[9];
    const unsigned int* mask1 = (const unsigned int*)d_in[10];
    const unsigned int* mask2 = (const unsigned int*)d_in[11];
    float* out = (float*)d_out;

    const int N = in_sizes[0] / 256;   // 50000
    const int E = in_sizes[1];         // 800000

    void *pA = nullptr, *pB = nullptr;
    cudaGetSymbolAddress(&pA, g_bufA);
    cudaGetSymbolAddress(&pB, g_bufB);
    float* bufA = (float*)pA;
    float* bufB = (float*)pB;

    // CSR build (reused by all 3 SpMM layers)
    zero_cnt_kernel<<<(N + 255) / 256, 256>>>(N);
    hist_kernel<<<(E + 255) / 256, 256>>>(rows, E);
    scan_kernel<<<1, 1024>>>(N);
    scatter_kernel<<<(E + 255) / 256, 256>>>(rows, cols, vals, E);

    // Layer 1: 256 -> 256
    dim3 g1((N + 127) / 128, 256 / 64);
    gemm_bias_kernel<256, 256><<<g1, 256>>>(x, W1, b1, bufA, N);
    spmm_kernel<256, true><<<(N + 7) / 8, 256>>>(bufA, mask1, bufB, N);

    // Layer 2: 256 -> 128
    dim3 g2((N + 127) / 128, 128 / 64);
    gemm_bias_kernel<256, 128><<<g2, 256>>>(bufB, W2, b2, bufA, N);
    spmm_kernel<128, true><<<(N + 7) / 8, 256>>>(bufA, mask2, bufB, N);

    // Layer 3: 128 -> 64 (no activation / mask on output)
    dim3 g3((N + 127) / 128, 1);
    gemm_bias_kernel<128, 64><<<g3, 256>>>(bufB, W3, b3, bufA, N);
    spmm_kernel<64, false><<<(N + 7) / 8, 256>>>(bufA, (const unsigned int*)nullptr, out, N);
}

// round 3
// speedup vs baseline: 1.0938x; 1.0938x over previous
#include <cuda_runtime.h>
#include <cstdint>

// ---------------------------------------------------------------------------
// ViewGCNEncoder: 3-layer GCN.
//   per layer: h = A_in @ W^T + b  (dense GEMM via 3xTF32 tensor-core mma)
//              s = SpMM(adj, h)    (segment-sum over edges, CSR, atomic-free)
//              s = leaky_relu(s); s = mask ? s*1.25 : 0   (layers 1,2 only)
// ---------------------------------------------------------------------------

#define NMAX 50000
#define EMAX 800000

__device__ float g_bufA[(size_t)NMAX * 256];
__device__ float g_bufB[(size_t)NMAX * 256];
__device__ int   g_cnt[NMAX];
__device__ int   g_rowptr[NMAX + 1];
__device__ int   g_cursor[NMAX];
__device__ int   g_ecol[EMAX];
__device__ float g_eval[EMAX];

// ---------------------------------------------------------------------------
// CSR construction
// ---------------------------------------------------------------------------
__global__ void zero_cnt_kernel(int n) {
    int i = blockIdx.x * blockDim.x + threadIdx.x;
    if (i < n) g_cnt[i] = 0;
}

__global__ void hist_kernel(const int* __restrict__ rows, int E) {
    int i = blockIdx.x * blockDim.x + threadIdx.x;
    if (i < E) atomicAdd(&g_cnt[rows[i]], 1);
}

__global__ void scan_kernel(int n) {
    __shared__ int partial[1024];
    int tid = threadIdx.x;
    int chunk = (n + 1023) >> 10;
    int beg = tid * chunk;
    int end = min(beg + chunk, n);
    int sum = 0;
    for (int i = beg; i < end; ++i) sum += g_cnt[i];
    partial[tid] = sum;
    __syncthreads();
    for (int d = 1; d < 1024; d <<= 1) {
        int add = (tid >= d) ? partial[tid - d] : 0;
        __syncthreads();
        partial[tid] += add;
        __syncthreads();
    }
    int run = partial[tid] - sum;
    for (int i = beg; i < end; ++i) {
        g_rowptr[i] = run;
        g_cursor[i] = run;
        run += g_cnt[i];
    }
    if (beg < n && end == n) g_rowptr[n] = run;
}

__global__ void scatter_kernel(const int* __restrict__ rows, const int* __restrict__ cols,
                               const float* __restrict__ vals, int E) {
    int i = blockIdx.x * blockDim.x + threadIdx.x;
    if (i < E) {
        int r = rows[i];
        int pos = atomicAdd(&g_cursor[r], 1);
        g_ecol[pos] = cols[i];
        g_eval[pos] = vals[i];
    }
}

// ---------------------------------------------------------------------------
// 3xTF32 tensor-core GEMM: C[N,ODIM] = A[N,KDIM] @ W[ODIM,KDIM]^T + bias
// Block 128x64, BK=16, 256 threads (8 warps, 32x32 per warp), m16n8k8 mma.
// A = A_hi + A_lo (tf32 split); C += Ah*Bh + Ah*Bl + Al*Bh  (~fp32 accuracy).
// ---------------------------------------------------------------------------
__device__ __forceinline__ float tf32r(float x) {
    uint32_t r;
    asm("cvt.rna.tf32.f32 %0, %1;" : "=r"(r) : "f"(x));
    return __uint_as_float(r);
}

__device__ __forceinline__ void mma_tf32(float c[4], const float a[4], const float b[2]) {
    asm volatile(
        "mma.sync.aligned.m16n8k8.row.col.f32.tf32.tf32.f32 "
        "{%0,%1,%2,%3},{%4,%5,%6,%7},{%8,%9},{%0,%1,%2,%3};"
        : "+f"(c[0]), "+f"(c[1]), "+f"(c[2]), "+f"(c[3])
        : "r"(__float_as_uint(a[0])), "r"(__float_as_uint(a[1])),
          "r"(__float_as_uint(a[2])), "r"(__float_as_uint(a[3])),
          "r"(__float_as_uint(b[0])), "r"(__float_as_uint(b[1])));
}

template <int KDIM, int ODIM>
__global__ __launch_bounds__(256) void gemm_tc_kernel(
    const float* __restrict__ A, const float* __restrict__ W,
    const float* __restrict__ bias, float* __restrict__ C, int N)
{
    constexpr int BM = 128, BK = 16;
    constexpr int ASTR = BM + 8;   // bank = (8k + m) % 32 -> conflict-free frags
    constexpr int BSTR = 64 + 8;

    __shared__ float As_hi[BK][ASTR];
    __shared__ float As_lo[BK][ASTR];
    __shared__ float Ws_hi[BK][BSTR];
    __shared__ float Ws_lo[BK][BSTR];

    const int tid  = threadIdx.x;
    const int m0   = blockIdx.x * BM;
    const int o0   = blockIdx.y * 64;
    const int warp = tid >> 5;
    const int lane = tid & 31;
    const int g    = lane >> 2;   // group id 0..7
    const int t4   = lane & 3;    // thread-in-group 0..3
    const int wm   = warp & 3;    // 4 warps along M (32 rows each)
    const int wn   = warp >> 2;   // 2 warps along N (32 cols each)

    const int ldm = tid >> 2;     // 0..63 (row for loads)
    const int ldq = tid & 3;      // float4 index along k

    float acc[2][4][4];
#pragma unroll
    for (int mt = 0; mt < 2; ++mt)
#pragma unroll
        for (int nt = 0; nt < 4; ++nt)
#pragma unroll
            for (int i = 0; i < 4; ++i) acc[mt][nt][i] = 0.f;

    for (int k0 = 0; k0 < KDIM; k0 += BK) {
        // load A tile 128x16 -> hi/lo (transposed to [k][m])
#pragma unroll
        for (int rep = 0; rep < 2; ++rep) {
            int mrow = ldm + rep * 64;
            int m = m0 + mrow;
            float4 v = make_float4(0.f, 0.f, 0.f, 0.f);
            if (m < N) v = *(const float4*)&A[(size_t)m * KDIM + k0 + ldq * 4];
            const float* vp = &v.x;
#pragma unroll
            for (int i = 0; i < 4; ++i) {
                float x  = vp[i];
                float hi = tf32r(x);
                As_hi[ldq * 4 + i][mrow] = hi;
                As_lo[ldq * 4 + i][mrow] = tf32r(x - hi);
            }
        }
        // load W tile 64x16 -> hi/lo
        {
            float4 v = *(const float4*)&W[(size_t)(o0 + ldm) * KDIM + k0 + ldq * 4];
            const float* vp = &v.x;
#pragma unroll
            for (int i = 0; i < 4; ++i) {
                float x  = vp[i];
                float hi = tf32r(x);
                Ws_hi[ldq * 4 + i][ldm] = hi;
                Ws_lo[ldq * 4 + i][ldm] = tf32r(x - hi);
            }
        }
        __syncthreads();

#pragma unroll
        for (int k8 = 0; k8 < 2; ++k8) {
            const int kk = k8 * 8 + t4;
            float a_hi[2][4], a_lo[2][4];
#pragma unroll
            for (int mt = 0; mt < 2; ++mt) {
                int mb = wm * 32 + mt * 16 + g;
                a_hi[mt][0] = As_hi[kk][mb];
                a_hi[mt][1] = As_hi[kk][mb + 8];
                a_hi[mt][2] = As_hi[kk + 4][mb];
                a_hi[mt][3] = As_hi[kk + 4][mb + 8];
                a_lo[mt][0] = As_lo[kk][mb];
                a_lo[mt][1] = As_lo[kk][mb + 8];
                a_lo[mt][2] = As_lo[kk + 4][mb];
                a_lo[mt][3] = As_lo[kk + 4][mb + 8];
            }
            float b_hi[4][2], b_lo[4][2];
#pragma unroll
            for (int nt = 0; nt < 4; ++nt) {
                int nb = wn * 32 + nt * 8 + g;
                b_hi[nt][0] = Ws_hi[kk][nb];
                b_hi[nt][1] = Ws_hi[kk + 4][nb];
                b_lo[nt][0] = Ws_lo[kk][nb];
                b_lo[nt][1] = Ws_lo[kk + 4][nb];
            }
#pragma unroll
            for (int mt = 0; mt < 2; ++mt)
#pragma unroll
                for (int nt = 0; nt < 4; ++nt) {
                    mma_tf32(acc[mt][nt], a_hi[mt], b_hi[nt]);
                    mma_tf32(acc[mt][nt], a_hi[mt], b_lo[nt]);
                    mma_tf32(acc[mt][nt], a_lo[mt], b_hi[nt]);
                }
        }
        __syncthreads();
    }

    // epilogue: bias + store (fragment layout: rows g, g+8; cols 2*t4, 2*t4+1)
#pragma unroll
    for (int mt = 0; mt < 2; ++mt) {
        int row0 = m0 + wm * 32 + mt * 16 + g;
#pragma unroll
        for (int nt = 0; nt < 4; ++nt) {
            int col = o0 + wn * 32 + nt * 8 + 2 * t4;
            float2 bv = *(const float2*)&bias[col];
            if (row0 < N) {
                float2 o = make_float2(acc[mt][nt][0] + bv.x, acc[mt][nt][1] + bv.y);
                *(float2*)&C[(size_t)row0 * ODIM + col] = o;
            }
            if (row0 + 8 < N) {
                float2 o = make_float2(acc[mt][nt][2] + bv.x, acc[mt][nt][3] + bv.y);
                *(float2*)&C[(size_t)(row0 + 8) * ODIM + col] = o;
            }
        }
    }
}

// ---------------------------------------------------------------------------
// CSR SpMM, warp-per-row, atomic-free, fused LeakyReLU + dropout mask.
// ---------------------------------------------------------------------------
__device__ __forceinline__ float leaky(float x) { return x >= 0.f ? x : 0.2f * x; }

template <int D, bool HAS_MASK>
__global__ __launch_bounds__(256) void spmm_kernel(
    const float* __restrict__ H, const unsigned int* __restrict__ mask,
    float* __restrict__ out, int N)
{
    const int warp = (blockIdx.x * blockDim.x + threadIdx.x) >> 5;
    const int lane = threadIdx.x & 31;
    if (warp >= N) return;
    const int r = warp;
    const int start = g_rowptr[r];
    const int end   = g_rowptr[r + 1];

    constexpr int V = D / 32;
    float acc[V];
#pragma unroll
    for (int v = 0; v < V; ++v) acc[v] = 0.f;

    for (int base = start; base < end; base += 32) {
        int e = base + lane;
        int c = 0;
        float v = 0.f;
        if (e < end) { c = g_ecol[e]; v = g_eval[e]; }
        int cnt = min(32, end - base);
#pragma unroll 4
        for (int j = 0; j < cnt; ++j) {
            int   cj = __shfl_sync(0xffffffffu, c, j);
            float vj = __shfl_sync(0xffffffffu, v, j);
            const float* hp = H + (size_t)cj * D;
            if (D == 256) {
                float4 a = *(const float4*)&hp[lane * 4];
                float4 b = *(const float4*)&hp[128 + lane * 4];
                acc[0] += vj * a.x; acc[1] += vj * a.y;
                acc[2] += vj * a.z; acc[3] += vj * a.w;
                acc[4] += vj * b.x; acc[5] += vj * b.y;
                acc[6] += vj * b.z; acc[7] += vj * b.w;
            } else if (D == 128) {
                float4 a = *(const float4*)&hp[lane * 4];
                acc[0] += vj * a.x; acc[1] += vj * a.y;
                acc[2] += vj * a.z; acc[3] += vj * a.w;
            } else {
                float2 a = *(const float2*)&hp[lane * 2];
                acc[0] += vj * a.x; acc[1] += vj * a.y;
            }
        }
    }

    const float keep = 1.25f;
    if (D == 256) {
        float4 o0, o1;
        if (HAS_MASK) {
            uint4 m0 = *(const uint4*)&mask[(size_t)r * D + lane * 4];
            uint4 m1 = *(const uint4*)&mask[(size_t)r * D + 128 + lane * 4];
            o0.x = m0.x ? leaky(acc[0]) * keep : 0.f;
            o0.y = m0.y ? leaky(acc[1]) * keep : 0.f;
            o0.z = m0.z ? leaky(acc[2]) * keep : 0.f;
            o0.w = m0.w ? leaky(acc[3]) * keep : 0.f;
            o1.x = m1.x ? leaky(acc[4]) * keep : 0.f;
            o1.y = m1.y ? leaky(acc[5]) * keep : 0.f;
            o1.z = m1.z ? leaky(acc[6]) * keep : 0.f;
            o1.w = m1.w ? leaky(acc[7]) * keep : 0.f;
        } else {
            o0 = make_float4(acc[0], acc[1], acc[2], acc[3]);
            o1 = make_float4(acc[4], acc[5], acc[6], acc[7]);
        }
        *(float4*)&out[(size_t)r * D + lane * 4] = o0;
        *(float4*)&out[(size_t)r * D + 128 + lane * 4] = o1;
    } else if (D == 128) {
        float4 o0;
        if (HAS_MASK) {
            uint4 m0 = *(const uint4*)&mask[(size_t)r * D + lane * 4];
            o0.x = m0.x ? leaky(acc[0]) * keep : 0.f;
            o0.y = m0.y ? leaky(acc[1]) * keep : 0.f;
            o0.z = m0.z ? leaky(acc[2]) * keep : 0.f;
            o0.w = m0.w ? leaky(acc[3]) * keep : 0.f;
        } else {
            o0 = make_float4(acc[0], acc[1], acc[2], acc[3]);
        }
        *(float4*)&out[(size_t)r * D + lane * 4] = o0;
    } else {
        float2 o0 = make_float2(acc[0], acc[1]);
        *(float2*)&out[(size_t)r * D + lane * 2] = o0;
    }
}

// ---------------------------------------------------------------------------
// Launch
// ---------------------------------------------------------------------------
extern "C" void kernel_launch(void* const* d_in, const int* in_sizes, int n_in,
                              void* d_out, int out_size)
{
    const float* x     = (const float*)d_in[0];
    const int*   rows  = (const int*)d_in[1];
    const int*   cols  = (const int*)d_in[2];
    const float* vals  = (const float*)d_in[3];
    const float* W1    = (const float*)d_in[4];
    const float* b1    = (const float*)d_in[5];
    const float* W2    = (const float*)d_in[6];
    const float* b2    = (const float*)d_in[7];
    const float* W3    = (const float*)d_in[8];
    const float* b3    = (const float*)d_in[9];
    const unsigned int* mask1 = (const unsigned int*)d_in[10];
    const unsigned int* mask2 = (const unsigned int*)d_in[11];
    float* out = (float*)d_out;

    const int N = in_sizes[0] / 256;
    const int E = in_sizes[1];

    void *pA = nullptr, *pB = nullptr;
    cudaGetSymbolAddress(&pA, g_bufA);
    cudaGetSymbolAddress(&pB, g_bufB);
    float* bufA = (float*)pA;
    float* bufB = (float*)pB;

    // CSR build (reused by all 3 SpMM layers)
    zero_cnt_kernel<<<(N + 255) / 256, 256>>>(N);
    hist_kernel<<<(E + 255) / 256, 256>>>(rows, E);
    scan_kernel<<<1, 1024>>>(N);
    scatter_kernel<<<(E + 255) / 256, 256>>>(rows, cols, vals, E);

    // Layer 1: 256 -> 256
    dim3 g1((N + 127) / 128, 256 / 64);
    gemm_tc_kernel<256, 256><<<g1, 256>>>(x, W1, b1, bufA, N);
    spmm_kernel<256, true><<<(N + 7) / 8, 256>>>(bufA, mask1, bufB, N);

    // Layer 2: 256 -> 128
    dim3 g2((N + 127) / 128, 128 / 64);
    gemm_tc_kernel<256, 128><<<g2, 256>>>(bufB, W2, b2, bufA, N);
    spmm_kernel<128, true><<<(N + 7) / 8, 256>>>(bufA, mask2, bufB, N);

    // Layer 3: 128 -> 64
    dim3 g3((N + 127) / 128, 1);
    gemm_tc_kernel<128, 64><<<g3, 256>>>(bufB, W3, b3, bufA, N);
    spmm_kernel<64, false><<<(N + 7) / 8, 256>>>(bufA, (const unsigned int*)nullptr, out, N);
}

// round 5
// speedup vs baseline: 1.4910x; 1.3631x over previous
#include <cuda_runtime.h>
#include <cuda_fp16.h>
#include <cstdint>

// ---------------------------------------------------------------------------
// ViewGCNEncoder: 3-layer GCN.
//   per layer: h = A_in @ W^T + b  (dense GEMM via fp16-split m16n8k16 mma)
//              s = SpMM(adj, h)    (segment-sum over edges, CSR, atomic-free)
//              s = leaky_relu(s); s = mask ? s*1.25 : 0   (layers 1,2 only)
// ---------------------------------------------------------------------------

#define NMAX 50000
#define EMAX 800000

__device__ float g_bufA[(size_t)NMAX * 256];
__device__ float g_bufB[(size_t)NMAX * 256];
__device__ int   g_cnt[NMAX];
__device__ int   g_rowptr[NMAX + 1];
__device__ int   g_cursor[NMAX];
__device__ int   g_ecol[EMAX];
__device__ float g_eval[EMAX];

// ---------------------------------------------------------------------------
// CSR construction
// ---------------------------------------------------------------------------
__global__ void hist_kernel(const int* __restrict__ rows, int E) {
    int i = blockIdx.x * blockDim.x + threadIdx.x;
    if (i < E) atomicAdd(&g_cnt[rows[i]], 1);
}

__global__ void scan_kernel(int n) {
    __shared__ int partial[1024];
    int tid = threadIdx.x;
    int chunk = (n + 1023) >> 10;
    int beg = tid * chunk;
    int end = min(beg + chunk, n);
    int sum = 0;
    for (int i = beg; i < end; ++i) sum += g_cnt[i];
    partial[tid] = sum;
    __syncthreads();
    for (int d = 1; d < 1024; d <<= 1) {
        int add = (tid >= d) ? partial[tid - d] : 0;
        __syncthreads();
        partial[tid] += add;
        __syncthreads();
    }
    int run = partial[tid] - sum;
    for (int i = beg; i < end; ++i) {
        g_rowptr[i] = run;
        g_cursor[i] = run;
        run += g_cnt[i];
    }
    if (beg < n && end == n) g_rowptr[n] = run;
}

__global__ void scatter_kernel(const int* __restrict__ rows, const int* __restrict__ cols,
                               const float* __restrict__ vals, int E) {
    int i = blockIdx.x * blockDim.x + threadIdx.x;
    if (i < E) {
        int r = rows[i];
        int pos = atomicAdd(&g_cursor[r], 1);
        g_ecol[pos] = cols[i];
        g_eval[pos] = vals[i];
    }
}

// ---------------------------------------------------------------------------
// fp16-split tensor-core GEMM: C[N,ODIM] = A[N,KDIM] @ W[ODIM,KDIM]^T + bias
// A = Ah + Al (fp16 halves); C += Ah*Bh + Ah*Bl + Al*Bh  (~2^-21 accuracy).
// Block 128x64, BK=16, 256 threads (8 warps, 32x32 per warp), m16n8k16 mma.
// ---------------------------------------------------------------------------
__device__ __forceinline__ void mma_f16(float c[4], const uint32_t a[4], const uint32_t b[2]) {
    asm volatile(
        "mma.sync.aligned.m16n8k16.row.col.f32.f16.f16.f32 "
        "{%0,%1,%2,%3},{%4,%5,%6,%7},{%8,%9},{%0,%1,%2,%3};"
        : "+f"(c[0]), "+f"(c[1]), "+f"(c[2]), "+f"(c[3])
        : "r"(a[0]), "r"(a[1]), "r"(a[2]), "r"(a[3]),
          "r"(b[0]), "r"(b[1]));
}

__device__ __forceinline__ void split2(float x, __half& hi, __half& lo) {
    hi = __float2half_rn(x);
    lo = __float2half_rn(x - __half2float(hi));
}

template <int KDIM, int ODIM>
__global__ __launch_bounds__(256) void gemm_tc_kernel(
    const float* __restrict__ A, const float* __restrict__ W,
    const float* __restrict__ bias, float* __restrict__ C, int N)
{
    constexpr int BM = 128, BK = 16, BK2 = BK / 2;
    constexpr int ASTR = BM + 8;   // half2 units; bank = (8*k2 + m) % 32
    constexpr int BSTR = 64 + 8;

    __shared__ __half2 As_hi[BK2][ASTR];
    __shared__ __half2 As_lo[BK2][ASTR];
    __shared__ __half2 Ws_hi[BK2][BSTR];
    __shared__ __half2 Ws_lo[BK2][BSTR];

    const int tid  = threadIdx.x;
    const int m0   = blockIdx.x * BM;
    const int o0   = blockIdx.y * 64;
    const int warp = tid >> 5;
    const int lane = tid & 31;
    const int g    = lane >> 2;   // 0..7
    const int t4   = lane & 3;    // 0..3
    const int wm   = warp & 3;    // 4 warps along M
    const int wn   = warp >> 2;   // 2 warps along N

    const int ldm = tid >> 2;     // 0..63
    const int ldq = tid & 3;      // float4 index along k

    float acc[2][4][4];
#pragma unroll
    for (int mt = 0; mt < 2; ++mt)
#pragma unroll
        for (int nt = 0; nt < 4; ++nt)
#pragma unroll
            for (int i = 0; i < 4; ++i) acc[mt][nt][i] = 0.f;

    for (int k0 = 0; k0 < KDIM; k0 += BK) {
        // A tile 128x16 -> hi/lo half2 (packed along k), layout [k2][m]
#pragma unroll
        for (int rep = 0; rep < 2; ++rep) {
            int mrow = ldm + rep * 64;
            int m = m0 + mrow;
            float4 v = make_float4(0.f, 0.f, 0.f, 0.f);
            if (m < N) v = *(const float4*)&A[(size_t)m * KDIM + k0 + ldq * 4];
            __half hx, lx, hy, ly, hz, lz, hw, lw;
            split2(v.x, hx, lx); split2(v.y, hy, ly);
            split2(v.z, hz, lz); split2(v.w, hw, lw);
            As_hi[ldq * 2 + 0][mrow] = __halves2half2(hx, hy);
            As_lo[ldq * 2 + 0][mrow] = __halves2half2(lx, ly);
            As_hi[ldq * 2 + 1][mrow] = __halves2half2(hz, hw);
            As_lo[ldq * 2 + 1][mrow] = __halves2half2(lz, lw);
        }
        // W tile 64x16 -> hi/lo
        {
            float4 v = *(const float4*)&W[(size_t)(o0 + ldm) * KDIM + k0 + ldq * 4];
            __half hx, lx, hy, ly, hz, lz, hw, lw;
            split2(v.x, hx, lx); split2(v.y, hy, ly);
            split2(v.z, hz, lz); split2(v.w, hw, lw);
            Ws_hi[ldq * 2 + 0][ldm] = __halves2half2(hx, hy);
            Ws_lo[ldq * 2 + 0][ldm] = __halves2half2(lx, ly);
            Ws_hi[ldq * 2 + 1][ldm] = __halves2half2(hz, hw);
            Ws_lo[ldq * 2 + 1][ldm] = __halves2half2(lz, lw);
        }
        __syncthreads();

        // fragments (m16n8k16): a0:(g, 2t4..+1) a1:(g+8,..) a2:(g, 2t4+8..+9) a3:(g+8,..)
        uint32_t a_hi[2][4], a_lo[2][4];
#pragma unroll
        for (int mt = 0; mt < 2; ++mt) {
            int mb = wm * 32 + mt * 16 + g;
            a_hi[mt][0] = *(const uint32_t*)&As_hi[t4][mb];
            a_hi[mt][1] = *(const uint32_t*)&As_hi[t4][mb + 8];
            a_hi[mt][2] = *(const uint32_t*)&As_hi[t4 + 4][mb];
            a_hi[mt][3] = *(const uint32_t*)&As_hi[t4 + 4][mb + 8];
            a_lo[mt][0] = *(const uint32_t*)&As_lo[t4][mb];
            a_lo[mt][1] = *(const uint32_t*)&As_lo[t4][mb + 8];
            a_lo[mt][2] = *(const uint32_t*)&As_lo[t4 + 4][mb];
            a_lo[mt][3] = *(const uint32_t*)&As_lo[t4 + 4][mb + 8];
        }
        uint32_t b_hi[4][2], b_lo[4][2];
#pragma unroll
        for (int nt = 0; nt < 4; ++nt) {
            int nb = wn * 32 + nt * 8 + g;
            b_hi[nt][0] = *(const uint32_t*)&Ws_hi[t4][nb];
            b_hi[nt][1] = *(const uint32_t*)&Ws_hi[t4 + 4][nb];
            b_lo[nt][0] = *(const uint32_t*)&Ws_lo[t4][nb];
            b_lo[nt][1] = *(const uint32_t*)&Ws_lo[t4 + 4][nb];
        }
#pragma unroll
        for (int mt = 0; mt < 2; ++mt)
#pragma unroll
            for (int nt = 0; nt < 4; ++nt) {
                mma_f16(acc[mt][nt], a_hi[mt], b_hi[nt]);
                mma_f16(acc[mt][nt], a_hi[mt], b_lo[nt]);
                mma_f16(acc[mt][nt], a_lo[mt], b_hi[nt]);
            }
        __syncthreads();
    }

    // epilogue: bias + store (c0,c1: row g; c2,c3: row g+8; cols 2t4,2t4+1)
#pragma unroll
    for (int mt = 0; mt < 2; ++mt) {
        int row0 = m0 + wm * 32 + mt * 16 + g;
#pragma unroll
        for (int nt = 0; nt < 4; ++nt) {
            int col = o0 + wn * 32 + nt * 8 + 2 * t4;
            float2 bv = *(const float2*)&bias[col];
            if (row0 < N) {
                float2 o = make_float2(acc[mt][nt][0] + bv.x, acc[mt][nt][1] + bv.y);
                *(float2*)&C[(size_t)row0 * ODIM + col] = o;
            }
            if (row0 + 8 < N) {
                float2 o = make_float2(acc[mt][nt][2] + bv.x, acc[mt][nt][3] + bv.y);
                *(float2*)&C[(size_t)(row0 + 8) * ODIM + col] = o;
            }
        }
    }
}

// ---------------------------------------------------------------------------
// CSR SpMM, warp-per-row, atomic-free, fused LeakyReLU + dropout mask.
// Streaming data (masks, outputs) uses .cs to keep gather target L2-resident.
// ---------------------------------------------------------------------------
__device__ __forceinline__ float leaky(float x) { return x >= 0.f ? x : 0.2f * x; }

template <int D, bool HAS_MASK>
__global__ __launch_bounds__(256) void spmm_kernel(
    const float* __restrict__ H, const unsigned int* __restrict__ mask,
    float* __restrict__ out, int N)
{
    const int warp = (blockIdx.x * blockDim.x + threadIdx.x) >> 5;
    const int lane = threadIdx.x & 31;
    if (warp >= N) return;
    const int r = warp;
    const int start = g_rowptr[r];
    const int end   = g_rowptr[r + 1];

    constexpr int V = D / 32;
    float acc[V];
#pragma unroll
    for (int v = 0; v < V; ++v) acc[v] = 0.f;

    for (int base = start; base < end; base += 32) {
        int e = base + lane;
        int c = 0;
        float v = 0.f;
        if (e < end) { c = g_ecol[e]; v = g_eval[e]; }
        int cnt = min(32, end - base);
#pragma unroll 4
        for (int j = 0; j < cnt; ++j) {
            int   cj = __shfl_sync(0xffffffffu, c, j);
            float vj = __shfl_sync(0xffffffffu, v, j);
            const float* hp = H + (size_t)cj * D;
            if (D == 256) {
                float4 a = *(const float4*)&hp[lane * 4];
                float4 b = *(const float4*)&hp[128 + lane * 4];
                acc[0] += vj * a.x; acc[1] += vj * a.y;
                acc[2] += vj * a.z; acc[3] += vj * a.w;
                acc[4] += vj * b.x; acc[5] += vj * b.y;
                acc[6] += vj * b.z; acc[7] += vj * b.w;
            } else if (D == 128) {
                float4 a = *(const float4*)&hp[lane * 4];
                acc[0] += vj * a.x; acc[1] += vj * a.y;
                acc[2] += vj * a.z; acc[3] += vj * a.w;
            } else {
                float2 a = *(const float2*)&hp[lane * 2];
                acc[0] += vj * a.x; acc[1] += vj * a.y;
            }
        }
    }

    const float keep = 1.25f;
    if (D == 256) {
        float4 o0, o1;
        if (HAS_MASK) {
            uint4 m0 = __ldcs((const uint4*)&mask[(size_t)r * D + lane * 4]);
            uint4 m1 = __ldcs((const uint4*)&mask[(size_t)r * D + 128 + lane * 4]);
            o0.x = m0.x ? leaky(acc[0]) * keep : 0.f;
            o0.y = m0.y ? leaky(acc[1]) * keep : 0.f;
            o0.z = m0.z ? leaky(acc[2]) * keep : 0.f;
            o0.w = m0.w ? leaky(acc[3]) * keep : 0.f;
            o1.x = m1.x ? leaky(acc[4]) * keep : 0.f;
            o1.y = m1.y ? leaky(acc[5]) * keep : 0.f;
            o1.z = m1.z ? leaky(acc[6]) * keep : 0.f;
            o1.w = m1.w ? leaky(acc[7]) * keep : 0.f;
        } else {
            o0 = make_float4(acc[0], acc[1], acc[2], acc[3]);
            o1 = make_float4(acc[4], acc[5], acc[6], acc[7]);
        }
        __stcs((float4*)&out[(size_t)r * D + lane * 4], o0);
        __stcs((float4*)&out[(size_t)r * D + 128 + lane * 4], o1);
    } else if (D == 128) {
        float4 o0;
        if (HAS_MASK) {
            uint4 m0 = __ldcs((const uint4*)&mask[(size_t)r * D + lane * 4]);
            o0.x = m0.x ? leaky(acc[0]) * keep : 0.f;
            o0.y = m0.y ? leaky(acc[1]) * keep : 0.f;
            o0.z = m0.z ? leaky(acc[2]) * keep : 0.f;
            o0.w = m0.w ? leaky(acc[3]) * keep : 0.f;
        } else {
            o0 = make_float4(acc[0], acc[1], acc[2], acc[3]);
        }
        __stcs((float4*)&out[(size_t)r * D + lane * 4], o0);
    } else {
        float2 o0 = make_float2(acc[0], acc[1]);
        __stcs((float2*)&out[(size_t)r * D + lane * 2], o0);
    }
}

// ---------------------------------------------------------------------------
// Launch
// ---------------------------------------------------------------------------
extern "C" void kernel_launch(void* const* d_in, const int* in_sizes, int n_in,
                              void* d_out, int out_size)
{
    const float* x     = (const float*)d_in[0];
    const int*   rows  = (const int*)d_in[1];
    const int*   cols  = (const int*)d_in[2];
    const float* vals  = (const float*)d_in[3];
    const float* W1    = (const float*)d_in[4];
    const float* b1    = (const float*)d_in[5];
    const float* W2    = (const float*)d_in[6];
    const float* b2    = (const float*)d_in[7];
    const float* W3    = (const float*)d_in[8];
    const float* b3    = (const float*)d_in[9];
    const unsigned int* mask1 = (const unsigned int*)d_in[10];
    const unsigned int* mask2 = (const unsigned int*)d_in[11];
    float* out = (float*)d_out;

    const int N = in_sizes[0] / 256;
    const int E = in_sizes[1];

    void *pA = nullptr, *pB = nullptr, *pCnt = nullptr;
    cudaGetSymbolAddress(&pA, g_bufA);
    cudaGetSymbolAddress(&pB, g_bufB);
    cudaGetSymbolAddress(&pCnt, g_cnt);
    float* bufA = (float*)pA;
    float* bufB = (float*)pB;

    // GEMM1 first (independent of CSR build)
    dim3 g1((N + 127) / 128, 256 / 64);
    gemm_tc_kernel<256, 256><<<g1, 256>>>(x, W1, b1, bufA, N);

    // CSR build (reused by all 3 SpMM layers)
    cudaMemsetAsync(pCnt, 0, (size_t)N * sizeof(int));
    hist_kernel<<<(E + 255) / 256, 256>>>(rows, E);
    scan_kernel<<<1, 1024>>>(N);
    scatter_kernel<<<(E + 255) / 256, 256>>>(rows, cols, vals, E);

    // Layer 1 SpMM
    spmm_kernel<256, true><<<(N + 7) / 8, 256>>>(bufA, mask1, bufB, N);

    // Layer 2: 256 -> 128
    dim3 g2((N + 127) / 128, 128 / 64);
    gemm_tc_kernel<256, 128><<<g2, 256>>>(bufB, W2, b2, bufA, N);
    spmm_kernel<128, true><<<(N + 7) / 8, 256>>>(bufA, mask2, bufB, N);

    // Layer 3: 128 -> 64
    dim3 g3((N + 127) / 128, 1);
    gemm_tc_kernel<128, 64><<<g3, 256>>>(bufB, W3, b3, bufA, N);
    spmm_kernel<64, false><<<(N + 7) / 8, 256>>>(bufA, (const unsigned int*)nullptr, out, N);
}

// round 6
// speedup vs baseline: 1.6085x; 1.0788x over previous
#include <cuda_runtime.h>
#include <cuda_fp16.h>
#include <cstdint>

// ---------------------------------------------------------------------------
// ViewGCNEncoder: 3-layer GCN.
//   per layer: h = A_in @ W^T + b  (fp16-split m16n8k16 mma GEMM, fp16 output)
//              s = SpMM(adj, h)    (CSR segment-sum; gathers fp16, accum fp32)
//              s = leaky_relu(s); s = mask ? s*1.25 : 0   (layers 1,2 only)
// ---------------------------------------------------------------------------

#define NMAX 50000
#define EMAX 800000

__device__ __half g_h16[(size_t)NMAX * 256];   // GEMM outputs (gather target)
__device__ float  g_bufB[(size_t)NMAX * 256];  // SpMM outputs (GEMM inputs)
__device__ int    g_cnt[NMAX];
__device__ int    g_rowptr[NMAX + 1];
__device__ int    g_cursor[NMAX];
__device__ int    g_ecol[EMAX];
__device__ float  g_eval[EMAX];

// ---------------------------------------------------------------------------
// CSR construction
// ---------------------------------------------------------------------------
__global__ void hist_kernel(const int* __restrict__ rows, int E) {
    int i = blockIdx.x * blockDim.x + threadIdx.x;
    if (i < E) atomicAdd(&g_cnt[rows[i]], 1);
}

__global__ void scan_kernel(int n) {
    __shared__ int partial[1024];
    int tid = threadIdx.x;
    int chunk = (n + 1023) >> 10;
    int beg = tid * chunk;
    int end = min(beg + chunk, n);
    int sum = 0;
    for (int i = beg; i < end; ++i) sum += g_cnt[i];
    partial[tid] = sum;
    __syncthreads();
    for (int d = 1; d < 1024; d <<= 1) {
        int add = (tid >= d) ? partial[tid - d] : 0;
        __syncthreads();
        partial[tid] += add;
        __syncthreads();
    }
    int run = partial[tid] - sum;
    for (int i = beg; i < end; ++i) {
        g_rowptr[i] = run;
        g_cursor[i] = run;
        run += g_cnt[i];
    }
    if (beg < n && end == n) g_rowptr[n] = run;
}

__global__ void scatter_kernel(const int* __restrict__ rows, const int* __restrict__ cols,
                               const float* __restrict__ vals, int E) {
    int i = blockIdx.x * blockDim.x + threadIdx.x;
    if (i < E) {
        int r = rows[i];
        int pos = atomicAdd(&g_cursor[r], 1);
        g_ecol[pos] = cols[i];
        g_eval[pos] = vals[i];
    }
}

// ---------------------------------------------------------------------------
// fp16-split tensor-core GEMM: C[N,ODIM] = A[N,KDIM] @ W[ODIM,KDIM]^T + bias
// A = Ah + Al (fp16 halves); C += Ah*Bh + Ah*Bl + Al*Bh  (~2^-21 accuracy).
// Output stored as fp16 (one rounding; feeds the SpMM gather).
// ---------------------------------------------------------------------------
__device__ __forceinline__ void mma_f16(float c[4], const uint32_t a[4], const uint32_t b[2]) {
    asm volatile(
        "mma.sync.aligned.m16n8k16.row.col.f32.f16.f16.f32 "
        "{%0,%1,%2,%3},{%4,%5,%6,%7},{%8,%9},{%0,%1,%2,%3};"
        : "+f"(c[0]), "+f"(c[1]), "+f"(c[2]), "+f"(c[3])
        : "r"(a[0]), "r"(a[1]), "r"(a[2]), "r"(a[3]),
          "r"(b[0]), "r"(b[1]));
}

__device__ __forceinline__ void split2(float x, __half& hi, __half& lo) {
    hi = __float2half_rn(x);
    lo = __float2half_rn(x - __half2float(hi));
}

template <int KDIM, int ODIM>
__global__ __launch_bounds__(256) void gemm_tc_kernel(
    const float* __restrict__ A, const float* __restrict__ W,
    const float* __restrict__ bias, __half* __restrict__ C, int N)
{
    constexpr int BM = 128, BK = 16, BK2 = BK / 2;
    constexpr int ASTR = BM + 8;
    constexpr int BSTR = 64 + 8;

    __shared__ __half2 As_hi[BK2][ASTR];
    __shared__ __half2 As_lo[BK2][ASTR];
    __shared__ __half2 Ws_hi[BK2][BSTR];
    __shared__ __half2 Ws_lo[BK2][BSTR];

    const int tid  = threadIdx.x;
    const int m0   = blockIdx.x * BM;
    const int o0   = blockIdx.y * 64;
    const int warp = tid >> 5;
    const int lane = tid & 31;
    const int g    = lane >> 2;
    const int t4   = lane & 3;
    const int wm   = warp & 3;
    const int wn   = warp >> 2;

    const int ldm = tid >> 2;
    const int ldq = tid & 3;

    float acc[2][4][4];
#pragma unroll
    for (int mt = 0; mt < 2; ++mt)
#pragma unroll
        for (int nt = 0; nt < 4; ++nt)
#pragma unroll
            for (int i = 0; i < 4; ++i) acc[mt][nt][i] = 0.f;

    for (int k0 = 0; k0 < KDIM; k0 += BK) {
#pragma unroll
        for (int rep = 0; rep < 2; ++rep) {
            int mrow = ldm + rep * 64;
            int m = m0 + mrow;
            float4 v = make_float4(0.f, 0.f, 0.f, 0.f);
            if (m < N) v = *(const float4*)&A[(size_t)m * KDIM + k0 + ldq * 4];
            __half hx, lx, hy, ly, hz, lz, hw, lw;
            split2(v.x, hx, lx); split2(v.y, hy, ly);
            split2(v.z, hz, lz); split2(v.w, hw, lw);
            As_hi[ldq * 2 + 0][mrow] = __halves2half2(hx, hy);
            As_lo[ldq * 2 + 0][mrow] = __halves2half2(lx, ly);
            As_hi[ldq * 2 + 1][mrow] = __halves2half2(hz, hw);
            As_lo[ldq * 2 + 1][mrow] = __halves2half2(lz, lw);
        }
        {
            float4 v = *(const float4*)&W[(size_t)(o0 + ldm) * KDIM + k0 + ldq * 4];
            __half hx, lx, hy, ly, hz, lz, hw, lw;
            split2(v.x, hx, lx); split2(v.y, hy, ly);
            split2(v.z, hz, lz); split2(v.w, hw, lw);
            Ws_hi[ldq * 2 + 0][ldm] = __halves2half2(hx, hy);
            Ws_lo[ldq * 2 + 0][ldm] = __halves2half2(lx, ly);
            Ws_hi[ldq * 2 + 1][ldm] = __halves2half2(hz, hw);
            Ws_lo[ldq * 2 + 1][ldm] = __halves2half2(lz, lw);
        }
        __syncthreads();

        uint32_t a_hi[2][4], a_lo[2][4];
#pragma unroll
        for (int mt = 0; mt < 2; ++mt) {
            int mb = wm * 32 + mt * 16 + g;
            a_hi[mt][0] = *(const uint32_t*)&As_hi[t4][mb];
            a_hi[mt][1] = *(const uint32_t*)&As_hi[t4][mb + 8];
            a_hi[mt][2] = *(const uint32_t*)&As_hi[t4 + 4][mb];
            a_hi[mt][3] = *(const uint32_t*)&As_hi[t4 + 4][mb + 8];
            a_lo[mt][0] = *(const uint32_t*)&As_lo[t4][mb];
            a_lo[mt][1] = *(const uint32_t*)&As_lo[t4][mb + 8];
            a_lo[mt][2] = *(const uint32_t*)&As_lo[t4 + 4][mb];
            a_lo[mt][3] = *(const uint32_t*)&As_lo[t4 + 4][mb + 8];
        }
        uint32_t b_hi[4][2], b_lo[4][2];
#pragma unroll
        for (int nt = 0; nt < 4; ++nt) {
            int nb = wn * 32 + nt * 8 + g;
            b_hi[nt][0] = *(const uint32_t*)&Ws_hi[t4][nb];
            b_hi[nt][1] = *(const uint32_t*)&Ws_hi[t4 + 4][nb];
            b_lo[nt][0] = *(const uint32_t*)&Ws_lo[t4][nb];
            b_lo[nt][1] = *(const uint32_t*)&Ws_lo[t4 + 4][nb];
        }
#pragma unroll
        for (int mt = 0; mt < 2; ++mt)
#pragma unroll
            for (int nt = 0; nt < 4; ++nt) {
                mma_f16(acc[mt][nt], a_hi[mt], b_hi[nt]);
                mma_f16(acc[mt][nt], a_hi[mt], b_lo[nt]);
                mma_f16(acc[mt][nt], a_lo[mt], b_hi[nt]);
            }
        __syncthreads();
    }

    // epilogue: bias, convert to fp16, store half2
#pragma unroll
    for (int mt = 0; mt < 2; ++mt) {
        int row0 = m0 + wm * 32 + mt * 16 + g;
#pragma unroll
        for (int nt = 0; nt < 4; ++nt) {
            int col = o0 + wn * 32 + nt * 8 + 2 * t4;
            float2 bv = *(const float2*)&bias[col];
            if (row0 < N) {
                __half2 o = __float22half2_rn(
                    make_float2(acc[mt][nt][0] + bv.x, acc[mt][nt][1] + bv.y));
                *(__half2*)&C[(size_t)row0 * ODIM + col] = o;
            }
            if (row0 + 8 < N) {
                __half2 o = __float22half2_rn(
                    make_float2(acc[mt][nt][2] + bv.x, acc[mt][nt][3] + bv.y));
                *(__half2*)&C[(size_t)(row0 + 8) * ODIM + col] = o;
            }
        }
    }
}

// ---------------------------------------------------------------------------
// CSR SpMM, warp-per-row, atomic-free. Gathers fp16 rows, accumulates fp32,
// fused LeakyReLU + dropout mask. Final layer writes fp32 output.
// ---------------------------------------------------------------------------
__device__ __forceinline__ float leaky(float x) { return x >= 0.f ? x : 0.2f * x; }

template <int D, bool HAS_MASK>
__global__ __launch_bounds__(256) void spmm_kernel(
    const __half* __restrict__ H, const unsigned int* __restrict__ mask,
    float* __restrict__ out, int N)
{
    const int warp = (blockIdx.x * blockDim.x + threadIdx.x) >> 5;
    const int lane = threadIdx.x & 31;
    if (warp >= N) return;
    const int r = warp;
    const int start = g_rowptr[r];
    const int end   = g_rowptr[r + 1];

    constexpr int V = D / 32;  // features per lane: 8, 4, 2
    float acc[V];
#pragma unroll
    for (int v = 0; v < V; ++v) acc[v] = 0.f;

    for (int base = start; base < end; base += 32) {
        int e = base + lane;
        int c = 0;
        float v = 0.f;
        if (e < end) { c = g_ecol[e]; v = g_eval[e]; }
        int cnt = min(32, end - base);
#pragma unroll 4
        for (int j = 0; j < cnt; ++j) {
            int   cj = __shfl_sync(0xffffffffu, c, j);
            float vj = __shfl_sync(0xffffffffu, v, j);
            const __half* hp = H + (size_t)cj * D + lane * V;
            if (D == 256) {
                uint4 raw = *(const uint4*)hp;   // 8 halves
                float2 f0 = __half22float2(*(const __half2*)&raw.x);
                float2 f1 = __half22float2(*(const __half2*)&raw.y);
                float2 f2 = __half22float2(*(const __half2*)&raw.z);
                float2 f3 = __half22float2(*(const __half2*)&raw.w);
                acc[0] += vj * f0.x; acc[1] += vj * f0.y;
                acc[2] += vj * f1.x; acc[3] += vj * f1.y;
                acc[4] += vj * f2.x; acc[5] += vj * f2.y;
                acc[6] += vj * f3.x; acc[7] += vj * f3.y;
            } else if (D == 128) {
                uint2 raw = *(const uint2*)hp;   // 4 halves
                float2 f0 = __half22float2(*(const __half2*)&raw.x);
                float2 f1 = __half22float2(*(const __half2*)&raw.y);
                acc[0] += vj * f0.x; acc[1] += vj * f0.y;
                acc[2] += vj * f1.x; acc[3] += vj * f1.y;
            } else {                              // D == 64: 2 halves
                uint32_t raw = *(const uint32_t*)hp;
                float2 f0 = __half22float2(*(const __half2*)&raw);
                acc[0] += vj * f0.x; acc[1] += vj * f0.y;
            }
        }
    }

    const float keep = 1.25f;
    float* op = out + (size_t)r * D + lane * V;
    if (D == 256) {
        float4 o0, o1;
        if (HAS_MASK) {
            const unsigned int* mp = mask + (size_t)r * D + lane * V;
            uint4 m0 = __ldcs((const uint4*)mp);
            uint4 m1 = __ldcs((const uint4*)(mp + 4));
            o0.x = m0.x ? leaky(acc[0]) * keep : 0.f;
            o0.y = m0.y ? leaky(acc[1]) * keep : 0.f;
            o0.z = m0.z ? leaky(acc[2]) * keep : 0.f;
            o0.w = m0.w ? leaky(acc[3]) * keep : 0.f;
            o1.x = m1.x ? leaky(acc[4]) * keep : 0.f;
            o1.y = m1.y ? leaky(acc[5]) * keep : 0.f;
            o1.z = m1.z ? leaky(acc[6]) * keep : 0.f;
            o1.w = m1.w ? leaky(acc[7]) * keep : 0.f;
        } else {
            o0 = make_float4(acc[0], acc[1], acc[2], acc[3]);
            o1 = make_float4(acc[4], acc[5], acc[6], acc[7]);
        }
        *(float4*)op = o0;
        *(float4*)(op + 4) = o1;
    } else if (D == 128) {
        float4 o0;
        if (HAS_MASK) {
            uint4 m0 = __ldcs((const uint4*)(mask + (size_t)r * D + lane * V));
            o0.x = m0.x ? leaky(acc[0]) * keep : 0.f;
            o0.y = m0.y ? leaky(acc[1]) * keep : 0.f;
            o0.z = m0.z ? leaky(acc[2]) * keep : 0.f;
            o0.w = m0.w ? leaky(acc[3]) * keep : 0.f;
        } else {
            o0 = make_float4(acc[0], acc[1], acc[2], acc[3]);
        }
        *(float4*)op = o0;
    } else {  // D == 64, final layer: direct store (streaming)
        __stcs((float2*)op, make_float2(acc[0], acc[1]));
    }
}

// ---------------------------------------------------------------------------
// Launch
// ---------------------------------------------------------------------------
extern "C" void kernel_launch(void* const* d_in, const int* in_sizes, int n_in,
                              void* d_out, int out_size)
{
    const float* x     = (const float*)d_in[0];
    const int*   rows  = (const int*)d_in[1];
    const int*   cols  = (const int*)d_in[2];
    const float* vals  = (const float*)d_in[3];
    const float* W1    = (const float*)d_in[4];
    const float* b1    = (const float*)d_in[5];
    const float* W2    = (const float*)d_in[6];
    const float* b2    = (const float*)d_in[7];
    const float* W3    = (const float*)d_in[8];
    const float* b3    = (const float*)d_in[9];
    const unsigned int* mask1 = (const unsigned int*)d_in[10];
    const unsigned int* mask2 = (const unsigned int*)d_in[11];
    float* out = (float*)d_out;

    const int N = in_sizes[0] / 256;
    const int E = in_sizes[1];

    void *pH = nullptr, *pB = nullptr, *pCnt = nullptr;
    cudaGetSymbolAddress(&pH, g_h16);
    cudaGetSymbolAddress(&pB, g_bufB);
    cudaGetSymbolAddress(&pCnt, g_cnt);
    __half* h16  = (__half*)pH;
    float*  bufB = (float*)pB;

    // GEMM1 first (independent of CSR build)
    dim3 g1((N + 127) / 128, 256 / 64);
    gemm_tc_kernel<256, 256><<<g1, 256>>>(x, W1, b1, h16, N);

    // CSR build (reused by all 3 SpMM layers)
    cudaMemsetAsync(pCnt, 0, (size_t)N * sizeof(int));
    hist_kernel<<<(E + 255) / 256, 256>>>(rows, E);
    scan_kernel<<<1, 1024>>>(N);
    scatter_kernel<<<(E + 255) / 256, 256>>>(rows, cols, vals, E);

    // Layer 1 SpMM
    spmm_kernel<256, true><<<(N + 7) / 8, 256>>>(h16, mask1, bufB, N);

    // Layer 2: 256 -> 128
    dim3 g2((N + 127) / 128, 128 / 64);
    gemm_tc_kernel<256, 128><<<g2, 256>>>(bufB, W2, b2, h16, N);
    spmm_kernel<128, true><<<(N + 7) / 8, 256>>>(h16, mask2, bufB, N);

    // Layer 3: 128 -> 64
    dim3 g3((N + 127) / 128, 1);
    gemm_tc_kernel<128, 64><<<g3, 256>>>(bufB, W3, b3, h16, N);
    spmm_kernel<64, false><<<(N + 7) / 8, 256>>>(h16, (const unsigned int*)nullptr, out, N);
}